// round 3
// baseline (speedup 1.0000x reference)
#include <cuda_runtime.h>
#include <cuda_bf16.h>
#include <cstdint>

#define N_ROWS  16384
#define DDIM    512
#define K_CODES 8192

#define MT 128          // rows per CTA
#define NT 128          // codes per N tile
#define KCH 64          // dims per K chunk
#define NCHUNK 8        // DDIM / KCH
#define NTILES 64       // K_CODES / NT
#define CAP 32
#define MARGIN 1.0e-3f

// ---- scratch (__device__ globals: no cudaMalloc allowed) --------------------
__device__ float  g_snorm[N_ROWS];
__device__ float  g_cnorm[K_CODES];
__device__ int    g_idx[N_ROWS];
__device__ double g_loss;
__device__ __nv_bfloat16 g_xbf[(size_t)N_ROWS * DDIM];
__device__ __nv_bfloat16 g_cbf[(size_t)K_CODES * DDIM];
__device__ int    g_ccount[N_ROWS];
__device__ int    g_cand[(size_t)N_ROWS * CAP];

// ---- dynamic smem layout -----------------------------------------------------
#define A_OFF       0            // 8 chunks x 16384 = 131072
#define B_OFF       131072       // 2 bufs x 16384  = 32768
#define CN_OFF      163840       // 512
#define RM_OFF      164352       // 512 (encoded row mins)
#define SMEM_SZ     164864

#define SW(o) ((o) ^ ((((uint32_t)(o)) >> 3) & 0x70u))

static __device__ __forceinline__ uint32_t smem_u32(const void* p) {
    uint32_t a;
    asm("{ .reg .u64 t; cvta.to.shared.u64 t, %1; cvt.u32.u64 %0, t; }"
        : "=r"(a) : "l"(p));
    return a;
}
static __device__ __forceinline__ void cp16(uint32_t dst, const void* src) {
    asm volatile("cp.async.ca.shared.global [%0], [%1], 16;"
                 :: "r"(dst), "l"(src) : "memory");
}
static __device__ __forceinline__ void cp_commit() {
    asm volatile("cp.async.commit_group;" ::: "memory");
}
template <int N>
static __device__ __forceinline__ void cp_wait() {
    asm volatile("cp.async.wait_group %0;" :: "n"(N) : "memory");
}
static __device__ __forceinline__ void ldm_x4(uint32_t* r, uint32_t a) {
    asm volatile("ldmatrix.sync.aligned.m8n8.x4.shared.b16 {%0,%1,%2,%3}, [%4];"
                 : "=r"(r[0]), "=r"(r[1]), "=r"(r[2]), "=r"(r[3]) : "r"(a));
}
static __device__ __forceinline__ void ldm_x2(uint32_t* r, uint32_t a) {
    asm volatile("ldmatrix.sync.aligned.m8n8.x2.shared.b16 {%0,%1}, [%2];"
                 : "=r"(r[0]), "=r"(r[1]) : "r"(a));
}
static __device__ __forceinline__ void mma16816(float* d, const uint32_t* a,
                                                const uint32_t* b) {
    asm volatile(
        "mma.sync.aligned.m16n8k16.row.col.f32.bf16.bf16.f32 "
        "{%0,%1,%2,%3}, {%4,%5,%6,%7}, {%8,%9}, {%0,%1,%2,%3};"
        : "+f"(d[0]), "+f"(d[1]), "+f"(d[2]), "+f"(d[3])
        : "r"(a[0]), "r"(a[1]), "r"(a[2]), "r"(a[3]), "r"(b[0]), "r"(b[1]));
}
// monotone float<->uint encoding for atomicMin
static __device__ __forceinline__ uint32_t fenc(float f) {
    uint32_t u = __float_as_uint(f);
    return (u & 0x80000000u) ? ~u : (u | 0x80000000u);
}
static __device__ __forceinline__ float fdec(uint32_t u) {
    u = (u & 0x80000000u) ? (u & 0x7FFFFFFFu) : ~u;
    return __uint_as_float(u);
}

// ---------------------------------------------------------------------------
// Kernel 1: bf16 convert + exact fp32 row norms; zero loss + candidate counts.
// ---------------------------------------------------------------------------
__global__ void convert_norm_kernel(const float* __restrict__ x,
                                    const float* __restrict__ cb) {
    int gtid = blockIdx.x * blockDim.x + threadIdx.x;
    if (gtid == 0) g_loss = 0.0;
    if (gtid < N_ROWS) g_ccount[gtid] = 0;
    int warp = gtid >> 5;
    int lane = threadIdx.x & 31;
    if (warp >= N_ROWS + K_CODES) return;
    bool isx = warp < N_ROWS;
    const float* base = isx ? x + (size_t)warp * DDIM
                            : cb + (size_t)(warp - N_ROWS) * DDIM;
    __nv_bfloat16* dst = isx ? g_xbf + (size_t)warp * DDIM
                             : g_cbf + (size_t)(warp - N_ROWS) * DDIM;
    float s = 0.f;
#pragma unroll
    for (int i = 0; i < DDIM / 32; i++) {
        float v = base[lane + i * 32];
        s += v * v;
        dst[lane + i * 32] = __float2bfloat16(v);
    }
#pragma unroll
    for (int o = 16; o; o >>= 1) s += __shfl_down_sync(0xffffffff, s, o);
    if (lane == 0) {
        if (isx) g_snorm[warp] = s;
        else     g_cnorm[warp - N_ROWS] = s;
    }
}

// ---------------------------------------------------------------------------
// Kernel 2: HMMA bf16 GEMM (t = z . c) + shared running-min candidate filter.
// CTA = 128 rows (A resident in smem), streams 64 N-tiles of 128 codes.
// ---------------------------------------------------------------------------
__global__ void __launch_bounds__(256, 1)
vq_gemm_kernel() {
    extern __shared__ char smem[];
    const uint32_t sb = smem_u32(smem);
    const int tid  = threadIdx.x;
    const int wid  = tid >> 5;
    const int lane = tid & 31;
    const int warpM = wid >> 2;          // 0..1  (64 rows each)
    const int warpN = wid & 3;           // 0..3  (32 cols each)
    const int row0 = blockIdx.x * MT;

    // ---- load resident A (128 x 512 bf16) into 8 SW128 chunk tiles ----
    {
        const __nv_bfloat16* xb = g_xbf + (size_t)row0 * DDIM;
        for (int i = tid; i < MT * NCHUNK * 8; i += 256) {
            int c = i >> 10;               // chunk
            int rs = i & 1023;
            int r = rs >> 3, s = rs & 7;
            uint4 v = *(const uint4*)(xb + (size_t)r * DDIM + c * KCH + s * 8);
            *(uint4*)(smem + A_OFF + c * 16384 + SW(r * 128 + s * 16)) = v;
        }
    }
    // row-min init
    if (tid < MT) ((uint32_t*)(smem + RM_OFF))[tid] = 0xFFFFFFFFu;
    __syncthreads();

    // per-lane fragment address bases
    const int arow = warpM * 64 + (lane & 7) + ((lane >> 3) & 1) * 8;
    const int akb  = (lane >> 4) * 16;
    const int li   = lane & 15;
    const int brow = warpN * 32 + (li & 7);
    const int bkb  = ((li >> 3) & 1) * 16;

    for (int t = 0; t < NTILES; t++) {
        if (tid < NT) ((float*)(smem + CN_OFF))[tid] = g_cnorm[t * NT + tid];
        const __nv_bfloat16* cbb = g_cbf + (size_t)t * NT * DDIM;

        float acc[4][4][4];
#pragma unroll
        for (int mi = 0; mi < 4; mi++)
#pragma unroll
            for (int ni = 0; ni < 4; ni++)
#pragma unroll
                for (int e = 0; e < 4; e++) acc[mi][ni][e] = 0.f;

        // prologue: B chunk 0
#pragma unroll
        for (int i = 0; i < 4; i++) {
            int seg = tid + i * 256;
            int r = seg >> 3, s = seg & 7;
            cp16(sb + B_OFF + SW(r * 128 + s * 16),
                 cbb + (size_t)r * DDIM + s * 8);
        }
        cp_commit();

        for (int c = 0; c < NCHUNK; c++) {
            if (c < NCHUNK - 1) {
                const int nb = (c + 1) & 1;
#pragma unroll
                for (int i = 0; i < 4; i++) {
                    int seg = tid + i * 256;
                    int r = seg >> 3, s = seg & 7;
                    cp16(sb + B_OFF + nb * 16384 + SW(r * 128 + s * 16),
                         cbb + (size_t)r * DDIM + (c + 1) * KCH + s * 8);
                }
                cp_commit();
                cp_wait<1>();
            } else {
                cp_wait<0>();
            }
            __syncthreads();

            const uint32_t abase = sb + A_OFF + c * 16384;
            const uint32_t bbase = sb + B_OFF + (c & 1) * 16384;
#pragma unroll
            for (int kk = 0; kk < 4; kk++) {
                uint32_t af[4][4], bf[4][2];
#pragma unroll
                for (int mi = 0; mi < 4; mi++)
                    ldm_x4(af[mi], abase +
                           SW((arow + mi * 16) * 128 + kk * 32 + akb));
#pragma unroll
                for (int ni = 0; ni < 4; ni++)
                    ldm_x2(bf[ni], bbase +
                           SW((brow + ni * 8) * 128 + kk * 32 + bkb));
#pragma unroll
                for (int mi = 0; mi < 4; mi++)
#pragma unroll
                    for (int ni = 0; ni < 4; ni++)
                        mma16816(acc[mi][ni], af[mi], bf[ni]);
            }
            __syncthreads();
        }

        // ---- epilogue: v = cn - 2t, shared running min, candidate collect ----
        const float* cn = (const float*)(smem + CN_OFF);
        uint32_t* rm = (uint32_t*)(smem + RM_OFF);
        float vv[4][4][4];
        float vmin[4][2];
#pragma unroll
        for (int mi = 0; mi < 4; mi++) { vmin[mi][0] = 3.4e38f; vmin[mi][1] = 3.4e38f; }
#pragma unroll
        for (int mi = 0; mi < 4; mi++)
#pragma unroll
            for (int ni = 0; ni < 4; ni++)
#pragma unroll
                for (int e = 0; e < 4; e++) {
                    float cne = cn[warpN * 32 + ni * 8 + (lane & 3) * 2 + (e & 1)];
                    float v = fmaf(-2.f, acc[mi][ni][e], cne);
                    vv[mi][ni][e] = v;
                    int h = e >> 1;
                    vmin[mi][h] = fminf(vmin[mi][h], v);
                }
        // quad reduce (lanes sharing a row differ only in lane&3)
#pragma unroll
        for (int mi = 0; mi < 4; mi++)
#pragma unroll
            for (int h = 0; h < 2; h++) {
                float v = vmin[mi][h];
                v = fminf(v, __shfl_xor_sync(0xffffffff, v, 1));
                v = fminf(v, __shfl_xor_sync(0xffffffff, v, 2));
                vmin[mi][h] = v;
            }
        if ((lane & 3) == 0) {
#pragma unroll
            for (int mi = 0; mi < 4; mi++)
#pragma unroll
                for (int h = 0; h < 2; h++)
                    atomicMin(&rm[warpM * 64 + mi * 16 + (lane >> 2) + h * 8],
                              fenc(vmin[mi][h]));
        }
        __syncthreads();
#pragma unroll
        for (int mi = 0; mi < 4; mi++)
#pragma unroll
            for (int h = 0; h < 2; h++) {
                int lrow = warpM * 64 + mi * 16 + (lane >> 2) + h * 8;
                float thr = fdec(rm[lrow]) + MARGIN;
                int grow = row0 + lrow;
#pragma unroll
                for (int ni = 0; ni < 4; ni++)
#pragma unroll
                    for (int j = 0; j < 2; j++) {
                        float v = vv[mi][ni][h * 2 + j];
                        if (v <= thr) {
                            int pos = atomicAdd(&g_ccount[grow], 1);
                            if (pos < CAP)
                                g_cand[(size_t)grow * CAP + pos] =
                                    t * NT + warpN * 32 + ni * 8 + (lane & 3) * 2 + j;
                        }
                    }
            }
        __syncthreads();   // protect cn/rowmin reads before next tile's writes
    }
}

// ---------------------------------------------------------------------------
// Kernel 3: exact fp32 rescoring (reference rounding, lowest-index ties).
// One warp per row.
// ---------------------------------------------------------------------------
__global__ void __launch_bounds__(256)
exact_kernel(const float* __restrict__ x, const float* __restrict__ cb) {
    int row = (blockIdx.x * blockDim.x + threadIdx.x) >> 5;
    int lane = threadIdx.x & 31;
    if (row >= N_ROWS) return;
    float xr[16];
    const float* xp = x + (size_t)row * DDIM;
#pragma unroll
    for (int e = 0; e < 16; e++) xr[e] = xp[lane + e * 32];
    const float s = g_snorm[row];
    const int cnt = g_ccount[row];
    float bd = 3.4e38f;
    int   bi = K_CODES;

    if (cnt <= CAP) {
        for (int i = 0; i < cnt; i++) {
            int k = g_cand[(size_t)row * CAP + i];
            const float* cp = cb + (size_t)k * DDIM;
            float t = 0.f;
#pragma unroll
            for (int e = 0; e < 16; e++) t = fmaf(xr[e], cp[lane + e * 32], t);
#pragma unroll
            for (int o = 16; o; o >>= 1) t += __shfl_xor_sync(0xffffffff, t, o);
            float dist = (s - 2.0f * t) + g_cnorm[k];
            if (dist < bd || (dist == bd && k < bi)) { bd = dist; bi = k; }
        }
    } else {  // overflow fallback: exact scan
        for (int k = 0; k < K_CODES; k++) {
            const float* cp = cb + (size_t)k * DDIM;
            float t = 0.f;
#pragma unroll
            for (int e = 0; e < 16; e++) t = fmaf(xr[e], cp[lane + e * 32], t);
#pragma unroll
            for (int o = 16; o; o >>= 1) t += __shfl_xor_sync(0xffffffff, t, o);
            float dist = (s - 2.0f * t) + g_cnorm[k];
            if (dist < bd) { bd = dist; bi = k; }
        }
    }
    if (lane == 0) g_idx[row] = bi;
}

// ---------------------------------------------------------------------------
// Kernel 4: gather z_q, straight-through output, fp64 loss accumulation.
// ---------------------------------------------------------------------------
__global__ void gather_loss_kernel(const float* __restrict__ x,
                                   const float* __restrict__ cb,
                                   float* __restrict__ out) {
    __shared__ double part[256];
    double lsum = 0.0;
    const size_t total = (size_t)N_ROWS * DDIM;
    for (size_t e = (size_t)blockIdx.x * blockDim.x + threadIdx.x;
         e < total; e += (size_t)gridDim.x * blockDim.x) {
        int n = (int)(e >> 9);
        int d = (int)(e & 511);
        int k = g_idx[n];
        float zq = cb[(size_t)k * DDIM + d];
        float ze = x[e];
        float diff = zq - ze;
        out[e] = ze + diff;
        lsum += (double)diff * (double)diff;
    }
    part[threadIdx.x] = lsum;
    __syncthreads();
    for (int s = 128; s; s >>= 1) {
        if (threadIdx.x < s) part[threadIdx.x] += part[threadIdx.x + s];
        __syncthreads();
    }
    if (threadIdx.x == 0) atomicAdd(&g_loss, part[0]);
}

// ---------------------------------------------------------------------------
// Kernel 5: losses + indices.
// ---------------------------------------------------------------------------
__global__ void finalize_kernel(float* __restrict__ out, long long out_size) {
    const long long base = (long long)N_ROWS * DDIM;
    if (blockIdx.x == 0 && threadIdx.x == 0 && out_size >= base + 2) {
        float loss = (float)(g_loss / ((double)N_ROWS * (double)DDIM));
        out[base]     = loss;
        out[base + 1] = loss;
    }
    if (out_size >= base + 2 + N_ROWS) {
        for (int n = blockIdx.x * blockDim.x + threadIdx.x; n < N_ROWS;
             n += gridDim.x * blockDim.x)
            out[base + 2 + n] = (float)g_idx[n];
    }
}

// ---------------------------------------------------------------------------
extern "C" void kernel_launch(void* const* d_in, const int* in_sizes, int n_in,
                              void* d_out, int out_size) {
    const float* x  = (const float*)d_in[0];
    const float* cb = (const float*)d_in[1];
    float* out = (float*)d_out;

    cudaFuncSetAttribute(vq_gemm_kernel,
                         cudaFuncAttributeMaxDynamicSharedMemorySize, SMEM_SZ);

    convert_norm_kernel<<<(N_ROWS + K_CODES) / 8, 256>>>(x, cb);
    vq_gemm_kernel<<<N_ROWS / MT, 256, SMEM_SZ>>>();
    exact_kernel<<<N_ROWS / 8, 256>>>(x, cb);
    gather_loss_kernel<<<2048, 256>>>(x, cb, out);
    finalize_kernel<<<64, 256>>>(out, (long long)out_size);
}